// round 1
// baseline (speedup 1.0000x reference)
#include <cuda_runtime.h>
#include <math.h>

// Fixed problem shape (per reference setup_inputs)
#define BB   2
#define NN   2048
#define CC   32
#define CP3  35          // C + 3
#define DD   32
#define DD2  1024        // D*D
#define BN   (BB*NN)     // 4096
#define KMAX 64

// Scratch (allocation-free rule: __device__ globals)
__device__ float g_A[(size_t)BN * DD2];   // pre @ W_r1            (16 MB)
__device__ float g_c[(size_t)BN * DD2];   // pre @ (W_r2-W_r1)+b_r (16 MB)
__device__ float g_v[BN * DD];            // relu(pre@W_v+b_v)
__device__ int   g_idx[BN * KMAX];        // flat neighbor indices (b*N+j)

// ---------------------------------------------------------------------------
// Kernel 1: exact KNN via shared-mem radix select (matches top_k tie-break)
// one block per query point, 256 threads
// ---------------------------------------------------------------------------
__global__ void knn_kernel(const float* __restrict__ xyz,
                           const int* __restrict__ knnp,
                           int* __restrict__ idx_out)
{
    __shared__ unsigned s_u[NN];
    __shared__ int      s_hist[256];
    __shared__ unsigned s_prefix;
    __shared__ int      s_rank, s_less, s_cnt, s_eqcnt;
    __shared__ int      s_eq[64];

    const int g    = blockIdx.x;          // 0..BN-1
    const int base = (g / NN) * NN;       // batch base
    const int tid  = threadIdx.x;
    const int K    = *knnp;

    const float xq = xyz[g*3+0], yq = xyz[g*3+1], zq = xyz[g*3+2];
    const float d2q = xq*xq + yq*yq + zq*zq;

    for (int j = tid; j < NN; j += 256) {
        const float x = xyz[(base+j)*3+0];
        const float y = xyz[(base+j)*3+1];
        const float z = xyz[(base+j)*3+2];
        const float d2j = x*x + y*y + z*z;
        const float dt  = x*xq + y*yq + z*zq;
        const float dist = (d2q + d2j) - 2.0f * dt;   // reference formula
        const unsigned bits = __float_as_uint(dist);
        s_u[j] = (bits & 0x80000000u) ? ~bits : (bits | 0x80000000u);
    }
    if (tid == 0) { s_prefix = 0u; s_rank = K; s_less = 0; s_cnt = 0; s_eqcnt = 0; }
    __syncthreads();

    // 4 x 8-bit MSB radix passes -> exact K-th smallest value
    for (int lvl = 0; lvl < 4; ++lvl) {
        const int shift = 24 - 8*lvl;
        s_hist[tid] = 0;
        __syncthreads();
        const unsigned pmask = (lvl == 0) ? 0u : (0xFFFFFFFFu << (shift + 8));
        const unsigned pref  = s_prefix;
        for (int j = tid; j < NN; j += 256) {
            const unsigned u = s_u[j];
            if ((u & pmask) == pref)
                atomicAdd(&s_hist[(u >> shift) & 255], 1);
        }
        __syncthreads();
        if (tid == 0) {
            int cum = 0;
            const int r = s_rank;
            for (int bk = 0; bk < 256; ++bk) {
                const int cn = s_hist[bk];
                if (cum + cn >= r) {
                    s_prefix = pref | ((unsigned)bk << shift);
                    s_rank   = r - cum;
                    s_less  += cum;
                    break;
                }
                cum += cn;
            }
        }
        __syncthreads();
    }

    const unsigned T = s_prefix;
    for (int j = tid; j < NN; j += 256) {
        const unsigned u = s_u[j];
        if (u < T) {
            const int p = atomicAdd(&s_cnt, 1);
            idx_out[(size_t)g*KMAX + p] = base + j;
        } else if (u == T) {
            const int p = atomicAdd(&s_eqcnt, 1);
            if (p < 64) s_eq[p] = j;
        }
    }
    __syncthreads();
    if (tid == 0) {
        // ties: smallest indices first (matches jax.lax.top_k)
        const int ne = min(s_eqcnt, 64);
        for (int i = 1; i < ne; ++i) {
            int v = s_eq[i], j2 = i - 1;
            while (j2 >= 0 && s_eq[j2] > v) { s_eq[j2+1] = s_eq[j2]; --j2; }
            s_eq[j2+1] = v;
        }
        const int need = K - s_cnt;
        for (int i = 0; i < need && i < ne; ++i)
            idx_out[(size_t)g*KMAX + s_cnt + i] = base + s_eq[i];
    }
}

// ---------------------------------------------------------------------------
// Kernel 2: A = pre @ W_r1 ; c = pre @ (W_r2 - W_r1) + b_r
// tile: 16 points x 128 cols, 256 threads
// ---------------------------------------------------------------------------
__global__ void prep_kernel(const float* __restrict__ feature,
                            const float* __restrict__ xyz,
                            const float* __restrict__ W_r,
                            const float* __restrict__ b_r)
{
    __shared__ float s_pre[16][CP3 + 1];
    __shared__ float s_w1[CP3][128];
    __shared__ float s_wd[CP3][128];

    const int p0  = blockIdx.x * 16;
    const int c0  = blockIdx.y * 128;
    const int tid = threadIdx.x;

    for (int t = tid; t < 16 * CP3; t += 256) {
        const int p = t / CP3, i = t % CP3;
        const int gg = p0 + p;
        s_pre[p][i] = (i < CC) ? feature[(size_t)gg*CC + i] : xyz[(size_t)gg*3 + (i - CC)];
    }
    for (int t = tid; t < CP3 * 128; t += 256) {
        const int i = t / 128, cc = t % 128;
        const float w1 = W_r[(size_t)i*DD2 + c0 + cc];
        const float w2 = W_r[(size_t)(CP3 + i)*DD2 + c0 + cc];
        s_w1[i][cc] = w1;
        s_wd[i][cc] = w2 - w1;
    }
    __syncthreads();

    const int cq = tid & 31;        // col group
    const int pr = tid >> 5;        // point (pr and pr+8)
    const int cb = cq * 4;

    float accA[2][4] = {{0,0,0,0},{0,0,0,0}};
    float accC[2][4] = {{0,0,0,0},{0,0,0,0}};

    #pragma unroll 5
    for (int i = 0; i < CP3; ++i) {
        const float pa = s_pre[pr][i];
        const float pb = s_pre[pr + 8][i];
        #pragma unroll
        for (int cc = 0; cc < 4; ++cc) {
            const float w1 = s_w1[i][cb + cc];
            const float wd = s_wd[i][cb + cc];
            accA[0][cc] = fmaf(pa, w1, accA[0][cc]);
            accA[1][cc] = fmaf(pb, w1, accA[1][cc]);
            accC[0][cc] = fmaf(pa, wd, accC[0][cc]);
            accC[1][cc] = fmaf(pb, wd, accC[1][cc]);
        }
    }

    #pragma unroll
    for (int pp = 0; pp < 2; ++pp) {
        const int gg = p0 + pr + pp * 8;
        const size_t off = (size_t)gg * DD2 + c0 + cb;
        float4 a4 = make_float4(accA[pp][0], accA[pp][1], accA[pp][2], accA[pp][3]);
        float4 c4 = make_float4(accC[pp][0] + b_r[c0+cb+0],
                                accC[pp][1] + b_r[c0+cb+1],
                                accC[pp][2] + b_r[c0+cb+2],
                                accC[pp][3] + b_r[c0+cb+3]);
        *reinterpret_cast<float4*>(&g_A[off]) = a4;
        *reinterpret_cast<float4*>(&g_c[off]) = c4;
    }
}

// ---------------------------------------------------------------------------
// Kernel 3: v = relu(pre @ W_v + b_v)
// ---------------------------------------------------------------------------
__global__ void v_kernel(const float* __restrict__ feature,
                         const float* __restrict__ xyz,
                         const float* __restrict__ W_v,
                         const float* __restrict__ b_v)
{
    const int t = blockIdx.x * 256 + threadIdx.x;
    if (t >= BN * DD) return;
    const int gg = t / DD, d = t % DD;
    float acc = b_v[d];
    #pragma unroll 8
    for (int i = 0; i < CC; ++i)
        acc = fmaf(feature[(size_t)gg*CC + i], W_v[i*DD + d], acc);
    #pragma unroll
    for (int i = 0; i < 3; ++i)
        acc = fmaf(xyz[(size_t)gg*3 + i], W_v[(CC + i)*DD + d], acc);
    g_v[t] = fmaxf(acc, 0.0f);
}

// ---------------------------------------------------------------------------
// Kernel 4: main aggregation.
// weight row (32 wide) = A[m] + c[n], normalized by (sum|.| + 32e-7), * sqrt(D)
// out[n,e] = sum_{k,d} gv[k,d] * w[d,e]; then out @ W_s + b_s.
// one block per point, 128 threads (4 warps x 32 lanes); warp w owns rows w,w+4,...
// ---------------------------------------------------------------------------
__global__ void main_kernel(const int* __restrict__ knnp,
                            const float* __restrict__ W_s,
                            const float* __restrict__ b_s,
                            float* __restrict__ out)
{
    __shared__ float s_c[DD2];
    __shared__ float s_gv[KMAX * DD];
    __shared__ int   s_idx[KMAX];
    __shared__ float s_part[4 * DD];

    const int g    = blockIdx.x;
    const int tid  = threadIdx.x;
    const int lane = tid & 31;
    const int w    = tid >> 5;
    const int K    = *knnp;

    if (tid < K) s_idx[tid] = g_idx[(size_t)g*KMAX + tid];
    for (int i = tid; i < DD2; i += 128) s_c[i] = g_c[(size_t)g*DD2 + i];
    __syncthreads();
    for (int t = tid; t < K * DD; t += 128) {
        const int k = t / DD, d = t % DD;
        s_gv[t] = g_v[(size_t)s_idx[k]*DD + d];
    }
    __syncthreads();

    const float SQRTD = 5.656854249492381f;   // sqrt(32)
    float acc = 0.0f;

    for (int k = 0; k < K; ++k) {
        const float* __restrict__ Ar = g_A + (size_t)s_idx[k] * DD2;
        float x[8];
        #pragma unroll
        for (int dd = 0; dd < 8; ++dd) {
            const int off = (w + dd*4) * DD + lane;
            x[dd] = __ldg(Ar + off) + s_c[off];
        }
        #pragma unroll
        for (int dd = 0; dd < 8; ++dd) {
            const int d = w + dd*4;
            float ax = fabsf(x[dd]);
            #pragma unroll
            for (int o = 16; o > 0; o >>= 1)
                ax += __shfl_xor_sync(0xFFFFFFFFu, ax, o);
            const float sc = __fdividef(SQRTD, ax + 3.2e-6f);  // + D*1e-7
            acc = fmaf(s_gv[k*DD + d] * sc, x[dd], acc);
        }
    }

    s_part[w * DD + lane] = acc;
    __syncthreads();

    if (w == 0) {
        float tot = s_part[lane] + s_part[DD + lane] + s_part[2*DD + lane] + s_part[3*DD + lane];
        // out @ W_s + b_s (cross-lane via shfl)
        float o2 = b_s[lane];
        #pragma unroll
        for (int e = 0; e < DD; ++e) {
            const float te = __shfl_sync(0xFFFFFFFFu, tot, e);
            o2 = fmaf(te, W_s[e*DD + lane], o2);
        }
        out[(size_t)g*DD + lane] = o2;
    }
}

// Write trailing N scalar if the harness output includes the tuple's second element
__global__ void tail_kernel(float* __restrict__ out, int pos, float val)
{
    out[pos] = val;
}

// ---------------------------------------------------------------------------
extern "C" void kernel_launch(void* const* d_in, const int* in_sizes, int n_in,
                              void* d_out, int out_size)
{
    const float* feature = (const float*)d_in[0];
    const float* xyz     = (const float*)d_in[1];
    const float* W_r     = (const float*)d_in[2];
    const float* b_r     = (const float*)d_in[3];
    const float* W_v     = (const float*)d_in[4];
    const float* b_v     = (const float*)d_in[5];
    const float* W_s     = (const float*)d_in[6];
    const float* b_s     = (const float*)d_in[7];
    const int*   knnp    = (const int*)d_in[8];
    float* out = (float*)d_out;

    int* idx_out;
    cudaGetSymbolAddress((void**)&idx_out, g_idx);  // host-side address query (no alloc)

    knn_kernel<<<BN, 256>>>(xyz, knnp, idx_out);
    prep_kernel<<<dim3(BN/16, DD2/128), 256>>>(feature, xyz, W_r, b_r);
    v_kernel<<<(BN*DD + 255)/256, 256>>>(feature, xyz, W_v, b_v);
    main_kernel<<<BN, 128>>>(knnp, W_s, b_s, out);

    const int total = BN * DD;
    if (out_size > total) {
        tail_kernel<<<1, 1>>>(out, total, (float)NN);
    }
}

// round 2
// speedup vs baseline: 1.3106x; 1.3106x over previous
#include <cuda_runtime.h>
#include <math.h>

// Fixed problem shape (per reference setup_inputs)
#define BB   2
#define NN   2048
#define CC   32
#define CP3  35          // C + 3
#define DD   32
#define DD2  1024        // D*D
#define BN   (BB*NN)     // 4096
#define KMAX 64
#define KPAD 40
#define PITCH 36         // row pitch in floats: 36*4=144B (16B aligned), conflict-free
#define KT   4           // k per stage round

// Scratch (allocation-free rule: __device__ globals)
__device__ float g_A[(size_t)BN * DD2];   // pre @ W_r1            (16 MB)
__device__ float g_c[(size_t)BN * DD2];   // pre @ (W_r2-W_r1)+b_r (16 MB)
__device__ float g_v[BN * DD];            // relu(pre@W_v+b_v)
__device__ int   g_idx[BN * KMAX];        // flat neighbor indices (b*N+j)

// ---------------------------------------------------------------------------
// Kernel 1: exact KNN via shared-mem radix select (matches top_k tie-break)
// one block per query point, 256 threads
// ---------------------------------------------------------------------------
__global__ void knn_kernel(const float* __restrict__ xyz,
                           const int* __restrict__ knnp,
                           int* __restrict__ idx_out)
{
    __shared__ unsigned s_u[NN];
    __shared__ int      s_hist[256];
    __shared__ unsigned s_prefix;
    __shared__ int      s_rank, s_cnt, s_eqcnt;
    __shared__ int      s_eq[64];

    const int g    = blockIdx.x;          // 0..BN-1
    const int base = (g / NN) * NN;       // batch base
    const int tid  = threadIdx.x;
    const int lane = tid & 31;
    const int K    = *knnp;

    const float xq = xyz[g*3+0], yq = xyz[g*3+1], zq = xyz[g*3+2];
    const float d2q = xq*xq + yq*yq + zq*zq;

    for (int j = tid; j < NN; j += 256) {
        const float x = xyz[(base+j)*3+0];
        const float y = xyz[(base+j)*3+1];
        const float z = xyz[(base+j)*3+2];
        const float d2j = x*x + y*y + z*z;
        const float dt  = x*xq + y*yq + z*zq;
        const float dist = (d2q + d2j) - 2.0f * dt;   // reference formula
        const unsigned bits = __float_as_uint(dist);
        s_u[j] = (bits & 0x80000000u) ? ~bits : (bits | 0x80000000u);
    }
    if (tid == 0) { s_prefix = 0u; s_rank = K; s_cnt = 0; s_eqcnt = 0; }
    __syncthreads();

    // 4 x 8-bit MSB radix passes -> exact K-th smallest value
    for (int lvl = 0; lvl < 4; ++lvl) {
        const int shift = 24 - 8*lvl;
        s_hist[tid] = 0;
        __syncthreads();
        const unsigned pmask = (lvl == 0) ? 0u : (0xFFFFFFFFu << (shift + 8));
        const unsigned pref  = s_prefix;
        const int      rk    = s_rank;
        __syncthreads();

        // histogram with warp-aggregated atomics
        for (int j = tid; j < NN; j += 256) {
            const unsigned u = s_u[j];
            const bool act = ((u & pmask) == pref);
            const unsigned bk = (u >> shift) & 255u;
            const unsigned mbk = act ? bk : 0xFFFFFFFFu;
            const unsigned mm  = __match_any_sync(0xFFFFFFFFu, mbk);
            const unsigned ab  = __ballot_sync(0xFFFFFFFFu, act);
            if (act) {
                const unsigned grp = mm & ab;
                if (lane == (__ffs(grp) - 1))
                    atomicAdd(&s_hist[bk], __popc(grp));
            }
        }
        __syncthreads();

        // warp-parallel bucket selection (threads 0..31, 8 buckets each)
        if (tid < 32) {
            const int lo = tid * 8;
            int h[8]; int lsum = 0;
            #pragma unroll
            for (int i = 0; i < 8; ++i) { h[i] = s_hist[lo + i]; lsum += h[i]; }
            int incl = lsum;
            #pragma unroll
            for (int o = 1; o < 32; o <<= 1) {
                int v = __shfl_up_sync(0xFFFFFFFFu, incl, o);
                if (tid >= o) incl += v;
            }
            const int excl = incl - lsum;
            if (excl < rk && rk <= incl) {
                int cum = excl;
                #pragma unroll
                for (int i = 0; i < 8; ++i) {
                    if (cum + h[i] >= rk) {
                        s_prefix = pref | ((unsigned)(lo + i) << shift);
                        s_rank   = rk - cum;
                        break;
                    }
                    cum += h[i];
                }
            }
        }
        __syncthreads();
    }

    const unsigned T = s_prefix;
    for (int j = tid; j < NN; j += 256) {
        const unsigned u = s_u[j];
        if (u < T) {
            const int p = atomicAdd(&s_cnt, 1);
            idx_out[(size_t)g*KMAX + p] = base + j;
        } else if (u == T) {
            const int p = atomicAdd(&s_eqcnt, 1);
            if (p < 64) s_eq[p] = j;
        }
    }
    __syncthreads();
    if (tid == 0) {
        // ties: smallest indices first (matches jax.lax.top_k)
        const int ne = min(s_eqcnt, 64);
        for (int i = 1; i < ne; ++i) {
            int v = s_eq[i], j2 = i - 1;
            while (j2 >= 0 && s_eq[j2] > v) { s_eq[j2+1] = s_eq[j2]; --j2; }
            s_eq[j2+1] = v;
        }
        const int need = K - s_cnt;
        for (int i = 0; i < need && i < ne; ++i)
            idx_out[(size_t)g*KMAX + s_cnt + i] = base + s_eq[i];
    }
}

// ---------------------------------------------------------------------------
// Kernel 2: A = pre @ W_r1 ; c = pre @ (W_r2 - W_r1) + b_r
// tile: 16 points x 128 cols, 256 threads
// ---------------------------------------------------------------------------
__global__ void prep_kernel(const float* __restrict__ feature,
                            const float* __restrict__ xyz,
                            const float* __restrict__ W_r,
                            const float* __restrict__ b_r)
{
    __shared__ float s_pre[16][CP3 + 1];
    __shared__ float s_w1[CP3][128];
    __shared__ float s_wd[CP3][128];

    const int p0  = blockIdx.x * 16;
    const int c0  = blockIdx.y * 128;
    const int tid = threadIdx.x;

    for (int t = tid; t < 16 * CP3; t += 256) {
        const int p = t / CP3, i = t % CP3;
        const int gg = p0 + p;
        s_pre[p][i] = (i < CC) ? feature[(size_t)gg*CC + i] : xyz[(size_t)gg*3 + (i - CC)];
    }
    for (int t = tid; t < CP3 * 128; t += 256) {
        const int i = t / 128, cc = t % 128;
        const float w1 = W_r[(size_t)i*DD2 + c0 + cc];
        const float w2 = W_r[(size_t)(CP3 + i)*DD2 + c0 + cc];
        s_w1[i][cc] = w1;
        s_wd[i][cc] = w2 - w1;
    }
    __syncthreads();

    const int cq = tid & 31;        // col group
    const int pr = tid >> 5;        // point (pr and pr+8)
    const int cb = cq * 4;

    float accA[2][4] = {{0,0,0,0},{0,0,0,0}};
    float accC[2][4] = {{0,0,0,0},{0,0,0,0}};

    #pragma unroll 5
    for (int i = 0; i < CP3; ++i) {
        const float pa = s_pre[pr][i];
        const float pb = s_pre[pr + 8][i];
        #pragma unroll
        for (int cc = 0; cc < 4; ++cc) {
            const float w1 = s_w1[i][cb + cc];
            const float wd = s_wd[i][cb + cc];
            accA[0][cc] = fmaf(pa, w1, accA[0][cc]);
            accA[1][cc] = fmaf(pb, w1, accA[1][cc]);
            accC[0][cc] = fmaf(pa, wd, accC[0][cc]);
            accC[1][cc] = fmaf(pb, wd, accC[1][cc]);
        }
    }

    #pragma unroll
    for (int pp = 0; pp < 2; ++pp) {
        const int gg = p0 + pr + pp * 8;
        const size_t off = (size_t)gg * DD2 + c0 + cb;
        float4 a4 = make_float4(accA[pp][0], accA[pp][1], accA[pp][2], accA[pp][3]);
        float4 c4 = make_float4(accC[pp][0] + b_r[c0+cb+0],
                                accC[pp][1] + b_r[c0+cb+1],
                                accC[pp][2] + b_r[c0+cb+2],
                                accC[pp][3] + b_r[c0+cb+3]);
        *reinterpret_cast<float4*>(&g_A[off]) = a4;
        *reinterpret_cast<float4*>(&g_c[off]) = c4;
    }
}

// ---------------------------------------------------------------------------
// Kernel 3: v = relu(pre @ W_v + b_v)
// ---------------------------------------------------------------------------
__global__ void v_kernel(const float* __restrict__ feature,
                         const float* __restrict__ xyz,
                         const float* __restrict__ W_v,
                         const float* __restrict__ b_v)
{
    const int t = blockIdx.x * 256 + threadIdx.x;
    if (t >= BN * DD) return;
    const int gg = t / DD, d = t % DD;
    float acc = b_v[d];
    #pragma unroll 8
    for (int i = 0; i < CC; ++i)
        acc = fmaf(feature[(size_t)gg*CC + i], W_v[i*DD + d], acc);
    #pragma unroll
    for (int i = 0; i < 3; ++i)
        acc = fmaf(xyz[(size_t)gg*3 + i], W_v[(CC + i)*DD + d], acc);
    g_v[t] = fmaxf(acc, 0.0f);
}

// ---------------------------------------------------------------------------
// Kernel 4: main aggregation, lane=d layout (no per-k shuffles).
// Stage x = A[m]+c into padded shared; each thread owns one full weight row,
// so the abs-row-sum is a serial register reduction.
// one block per point, 128 threads = 4 warps; warp = k_local, lane = d.
// ---------------------------------------------------------------------------
__global__ void __launch_bounds__(128, 4)
main_kernel(const int* __restrict__ knnp,
            const float* __restrict__ W_s,
            const float* __restrict__ b_s,
            float* __restrict__ out)
{
    __shared__ float s_x[KT][32 * PITCH];    // 4 * 4608 B
    __shared__ float s_gv[KPAD * DD];
    __shared__ int   s_idx[KPAD];
    __shared__ float s_fin[4][DD];

    const int g    = blockIdx.x;
    const int tid  = threadIdx.x;
    const int lane = tid & 31;
    const int w    = tid >> 5;
    const int K    = *knnp;

    if (tid < K) s_idx[tid] = g_idx[(size_t)g*KMAX + tid];
    __syncthreads();
    for (int t = tid; t < K * DD; t += 128)
        s_gv[t] = g_v[(size_t)s_idx[t >> 5]*DD + (t & 31)];

    // c held in registers (8 floats/thread); staging address precomputed
    const size_t cbase = (size_t)g * DD2 + tid * 8;
    const float4 c0 = *reinterpret_cast<const float4*>(g_c + cbase);
    const float4 c1 = *reinterpret_cast<const float4*>(g_c + cbase + 4);
    const int sd = (tid * 8) >> 5;           // staged row
    const int se = (tid * 8) & 31;           // staged col
    const int saddr = sd * PITCH + se;

    float acc[DD];
    #pragma unroll
    for (int e = 0; e < DD; ++e) acc[e] = 0.0f;

    for (int k0 = 0; k0 < K; k0 += KT) {
        const int tn = min(KT, K - k0);
        // stage x = A[m_k] + c for tn neighbors
        for (int kk = 0; kk < tn; ++kk) {
            const float* Ar = g_A + (size_t)s_idx[k0 + kk]*DD2 + tid*8;
            float4 a0 = *reinterpret_cast<const float4*>(Ar);
            float4 a1 = *reinterpret_cast<const float4*>(Ar + 4);
            a0.x += c0.x; a0.y += c0.y; a0.z += c0.z; a0.w += c0.w;
            a1.x += c1.x; a1.y += c1.y; a1.z += c1.z; a1.w += c1.w;
            *reinterpret_cast<float4*>(&s_x[kk][saddr])     = a0;
            *reinterpret_cast<float4*>(&s_x[kk][saddr + 4]) = a1;
        }
        __syncthreads();
        if (w < tn) {
            float x[DD];
            #pragma unroll
            for (int i = 0; i < 8; ++i) {
                const float4 v4 = *reinterpret_cast<const float4*>(&s_x[w][lane*PITCH + i*4]);
                x[i*4+0] = v4.x; x[i*4+1] = v4.y; x[i*4+2] = v4.z; x[i*4+3] = v4.w;
            }
            float rs = 0.0f;
            #pragma unroll
            for (int e = 0; e < DD; ++e) rs += fabsf(x[e]);
            const float sc   = __fdividef(5.656854249492381f, rs + 3.2e-6f); // sqrt(32)/(sum+D*1e-7)
            const float coef = s_gv[(k0 + w)*DD + lane] * sc;
            #pragma unroll
            for (int e = 0; e < DD; ++e) acc[e] = fmaf(coef, x[e], acc[e]);
        }
        __syncthreads();
    }

    // one-time reduction: warp-reduce each of the 32 output lanes
    #pragma unroll
    for (int e = 0; e < DD; ++e) {
        float v = acc[e];
        v += __shfl_xor_sync(0xFFFFFFFFu, v, 16);
        v += __shfl_xor_sync(0xFFFFFFFFu, v, 8);
        v += __shfl_xor_sync(0xFFFFFFFFu, v, 4);
        v += __shfl_xor_sync(0xFFFFFFFFu, v, 2);
        v += __shfl_xor_sync(0xFFFFFFFFu, v, 1);
        if (lane == 0) s_fin[w][e] = v;
    }
    __syncthreads();

    if (w == 0) {
        const float tot = s_fin[0][lane] + s_fin[1][lane] + s_fin[2][lane] + s_fin[3][lane];
        float o2 = b_s[lane];
        #pragma unroll
        for (int e = 0; e < DD; ++e) {
            const float te = __shfl_sync(0xFFFFFFFFu, tot, e);
            o2 = fmaf(te, W_s[e*DD + lane], o2);
        }
        out[(size_t)g*DD + lane] = o2;
    }
}

// Write trailing N scalar if the harness output includes the tuple's second element
__global__ void tail_kernel(float* __restrict__ out, int pos, float val)
{
    out[pos] = val;
}

// ---------------------------------------------------------------------------
extern "C" void kernel_launch(void* const* d_in, const int* in_sizes, int n_in,
                              void* d_out, int out_size)
{
    const float* feature = (const float*)d_in[0];
    const float* xyz     = (const float*)d_in[1];
    const float* W_r     = (const float*)d_in[2];
    const float* b_r     = (const float*)d_in[3];
    const float* W_v     = (const float*)d_in[4];
    const float* b_v     = (const float*)d_in[5];
    const float* W_s     = (const float*)d_in[6];
    const float* b_s     = (const float*)d_in[7];
    const int*   knnp    = (const int*)d_in[8];
    float* out = (float*)d_out;

    int* idx_out;
    cudaGetSymbolAddress((void**)&idx_out, g_idx);  // host-side address query (no alloc)

    knn_kernel<<<BN, 256>>>(xyz, knnp, idx_out);
    prep_kernel<<<dim3(BN/16, DD2/128), 256>>>(feature, xyz, W_r, b_r);
    v_kernel<<<(BN*DD + 255)/256, 256>>>(feature, xyz, W_v, b_v);
    main_kernel<<<BN, 128>>>(knnp, W_s, b_s, out);

    const int total = BN * DD;
    if (out_size > total) {
        tail_kernel<<<1, 1>>>(out, total, (float)NN);
    }
}

// round 3
// speedup vs baseline: 1.7474x; 1.3333x over previous
#include <cuda_runtime.h>
#include <math.h>

// Fixed problem shape (per reference setup_inputs)
#define BB   2
#define NN   2048
#define CC   32
#define CP3  35          // C + 3
#define DD   32
#define DD2  1024        // D*D
#define BN   (BB*NN)     // 4096
#define KMAX 64

// Scratch (allocation-free rule: __device__ globals)
// A and c stored in "quad" layout per point: flat index (e>>2)*128 + d*4 + (e&3)
// where weight[d][e], so a warp (lane=d) reads row-slices as coalesced float4s.
__device__ float g_A[(size_t)BN * DD2];   // pre @ W_r1            (16 MB)
__device__ float g_c[(size_t)BN * DD2];   // pre @ (W_r2-W_r1)+b_r (16 MB)
__device__ float g_v[BN * DD];            // relu(pre@W_v+b_v)
__device__ int   g_idx[BN * KMAX];        // flat neighbor indices (b*N+j)

// ---------------------------------------------------------------------------
// Kernel 1: exact KNN via shared-mem radix select (matches top_k tie-break)
// one block per query point, 256 threads
// ---------------------------------------------------------------------------
__global__ void knn_kernel(const float* __restrict__ xyz,
                           const int* __restrict__ knnp,
                           int* __restrict__ idx_out)
{
    __shared__ unsigned s_u[NN];
    __shared__ int      s_hist[256];
    __shared__ unsigned s_prefix;
    __shared__ int      s_rank, s_cnt, s_eqcnt;
    __shared__ int      s_eq[64];

    const int g    = blockIdx.x;          // 0..BN-1
    const int base = (g / NN) * NN;       // batch base
    const int tid  = threadIdx.x;
    const int lane = tid & 31;
    const int K    = *knnp;

    const float xq = xyz[g*3+0], yq = xyz[g*3+1], zq = xyz[g*3+2];
    const float d2q = xq*xq + yq*yq + zq*zq;

    for (int j = tid; j < NN; j += 256) {
        const float x = xyz[(base+j)*3+0];
        const float y = xyz[(base+j)*3+1];
        const float z = xyz[(base+j)*3+2];
        const float d2j = x*x + y*y + z*z;
        const float dt  = x*xq + y*yq + z*zq;
        const float dist = (d2q + d2j) - 2.0f * dt;   // reference formula
        const unsigned bits = __float_as_uint(dist);
        s_u[j] = (bits & 0x80000000u) ? ~bits : (bits | 0x80000000u);
    }
    if (tid == 0) { s_prefix = 0u; s_rank = K; s_cnt = 0; s_eqcnt = 0; }
    __syncthreads();

    // 4 x 8-bit MSB radix passes -> exact K-th smallest value
    for (int lvl = 0; lvl < 4; ++lvl) {
        const int shift = 24 - 8*lvl;
        s_hist[tid] = 0;
        __syncthreads();
        const unsigned pmask = (lvl == 0) ? 0u : (0xFFFFFFFFu << (shift + 8));
        const unsigned pref  = s_prefix;
        const int      rk    = s_rank;
        __syncthreads();

        // histogram with warp-aggregated atomics
        for (int j = tid; j < NN; j += 256) {
            const unsigned u = s_u[j];
            const bool act = ((u & pmask) == pref);
            const unsigned bk = (u >> shift) & 255u;
            const unsigned mbk = act ? bk : 0xFFFFFFFFu;
            const unsigned mm  = __match_any_sync(0xFFFFFFFFu, mbk);
            const unsigned ab  = __ballot_sync(0xFFFFFFFFu, act);
            if (act) {
                const unsigned grp = mm & ab;
                if (lane == (__ffs(grp) - 1))
                    atomicAdd(&s_hist[bk], __popc(grp));
            }
        }
        __syncthreads();

        // warp-parallel bucket selection (threads 0..31, 8 buckets each)
        if (tid < 32) {
            const int lo = tid * 8;
            int h[8]; int lsum = 0;
            #pragma unroll
            for (int i = 0; i < 8; ++i) { h[i] = s_hist[lo + i]; lsum += h[i]; }
            int incl = lsum;
            #pragma unroll
            for (int o = 1; o < 32; o <<= 1) {
                int v = __shfl_up_sync(0xFFFFFFFFu, incl, o);
                if (tid >= o) incl += v;
            }
            const int excl = incl - lsum;
            if (excl < rk && rk <= incl) {
                int cum = excl;
                #pragma unroll
                for (int i = 0; i < 8; ++i) {
                    if (cum + h[i] >= rk) {
                        s_prefix = pref | ((unsigned)(lo + i) << shift);
                        s_rank   = rk - cum;
                        break;
                    }
                    cum += h[i];
                }
            }
        }
        __syncthreads();
    }

    const unsigned T = s_prefix;
    for (int j = tid; j < NN; j += 256) {
        const unsigned u = s_u[j];
        if (u < T) {
            const int p = atomicAdd(&s_cnt, 1);
            idx_out[(size_t)g*KMAX + p] = base + j;
        } else if (u == T) {
            const int p = atomicAdd(&s_eqcnt, 1);
            if (p < 64) s_eq[p] = j;
        }
    }
    __syncthreads();
    if (tid == 0) {
        // ties: smallest indices first (matches jax.lax.top_k)
        const int ne = min(s_eqcnt, 64);
        for (int i = 1; i < ne; ++i) {
            int v = s_eq[i], j2 = i - 1;
            while (j2 >= 0 && s_eq[j2] > v) { s_eq[j2+1] = s_eq[j2]; --j2; }
            s_eq[j2+1] = v;
        }
        const int need = K - s_cnt;
        for (int i = 0; i < need && i < ne; ++i)
            idx_out[(size_t)g*KMAX + s_cnt + i] = base + s_eq[i];
    }
}

// ---------------------------------------------------------------------------
// Kernel 2: A = pre @ W_r1 ; c = pre @ (W_r2 - W_r1) + b_r   (quad layout)
// tile: 16 points x 128 cols, 256 threads
// ---------------------------------------------------------------------------
__global__ void prep_kernel(const float* __restrict__ feature,
                            const float* __restrict__ xyz,
                            const float* __restrict__ W_r,
                            const float* __restrict__ b_r)
{
    __shared__ float s_pre[16][CP3 + 1];
    __shared__ float s_w1[CP3][128];
    __shared__ float s_wd[CP3][128];

    const int p0  = blockIdx.x * 16;
    const int c0  = blockIdx.y * 128;
    const int tid = threadIdx.x;

    for (int t = tid; t < 16 * CP3; t += 256) {
        const int p = t / CP3, i = t % CP3;
        const int gg = p0 + p;
        s_pre[p][i] = (i < CC) ? feature[(size_t)gg*CC + i] : xyz[(size_t)gg*3 + (i - CC)];
    }
    for (int t = tid; t < CP3 * 128; t += 256) {
        const int i = t / 128, cc = t % 128;
        const float w1 = W_r[(size_t)i*DD2 + c0 + cc];
        const float w2 = W_r[(size_t)(CP3 + i)*DD2 + c0 + cc];
        s_w1[i][cc] = w1;
        s_wd[i][cc] = w2 - w1;
    }
    __syncthreads();

    const int cq = tid & 31;        // col group
    const int pr = tid >> 5;        // point (pr and pr+8)
    const int cb = cq * 4;

    float accA[2][4] = {{0,0,0,0},{0,0,0,0}};
    float accC[2][4] = {{0,0,0,0},{0,0,0,0}};

    #pragma unroll 5
    for (int i = 0; i < CP3; ++i) {
        const float pa = s_pre[pr][i];
        const float pb = s_pre[pr + 8][i];
        #pragma unroll
        for (int cc = 0; cc < 4; ++cc) {
            const float w1 = s_w1[i][cb + cc];
            const float wd = s_wd[i][cb + cc];
            accA[0][cc] = fmaf(pa, w1, accA[0][cc]);
            accA[1][cc] = fmaf(pb, w1, accA[1][cc]);
            accC[0][cc] = fmaf(pa, wd, accC[0][cc]);
            accC[1][cc] = fmaf(pb, wd, accC[1][cc]);
        }
    }

    // quad-layout destination: col = d*32 + e ; flat_q = (e>>2)*128 + d*4 + (e&3)
    const int col0 = c0 + cb;              // multiple of 4
    const int dRow = col0 >> 5;
    const int eBase = col0 & 31;           // multiple of 4
    const int qoff = (eBase >> 2) * 128 + dRow * 4;

    #pragma unroll
    for (int pp = 0; pp < 2; ++pp) {
        const int gg = p0 + pr + pp * 8;
        const size_t off = (size_t)gg * DD2 + qoff;
        float4 a4 = make_float4(accA[pp][0], accA[pp][1], accA[pp][2], accA[pp][3]);
        float4 c4 = make_float4(accC[pp][0] + b_r[col0+0],
                                accC[pp][1] + b_r[col0+1],
                                accC[pp][2] + b_r[col0+2],
                                accC[pp][3] + b_r[col0+3]);
        *reinterpret_cast<float4*>(&g_A[off]) = a4;
        *reinterpret_cast<float4*>(&g_c[off]) = c4;
    }
}

// ---------------------------------------------------------------------------
// Kernel 3: v = relu(pre @ W_v + b_v)
// ---------------------------------------------------------------------------
__global__ void v_kernel(const float* __restrict__ feature,
                         const float* __restrict__ xyz,
                         const float* __restrict__ W_v,
                         const float* __restrict__ b_v)
{
    const int t = blockIdx.x * 256 + threadIdx.x;
    if (t >= BN * DD) return;
    const int gg = t / DD, d = t % DD;
    float acc = b_v[d];
    #pragma unroll 8
    for (int i = 0; i < CC; ++i)
        acc = fmaf(feature[(size_t)gg*CC + i], W_v[i*DD + d], acc);
    #pragma unroll
    for (int i = 0; i < 3; ++i)
        acc = fmaf(xyz[(size_t)gg*3 + i], W_v[(CC + i)*DD + d], acc);
    g_v[t] = fmaxf(acc, 0.0f);
}

// ---------------------------------------------------------------------------
// Kernel 4: main aggregation, direct-LDG quad layout.
// 256 threads = 8 warps = 2 points (4 warps/point). lane = d (weight row).
// Per k: 8 coalesced LDG.128 of the A-row slice, row abs-sum in registers,
// accumulate acc[e] in registers. No smem staging, no per-k sync/shuffles.
// ---------------------------------------------------------------------------
__global__ void __launch_bounds__(256)
main_kernel(const int* __restrict__ knnp,
            const float* __restrict__ W_s,
            const float* __restrict__ b_s,
            float* __restrict__ out)
{
    __shared__ float s_fin[8][DD];

    const int tid  = threadIdx.x;
    const int lane = tid & 31;
    const int w    = tid >> 5;
    const int pw   = w >> 2;             // point within block (0/1)
    const int wq   = w & 3;              // warp within point
    const int g    = blockIdx.x * 2 + pw;
    const int K    = *knnp;

    // c for this point (quad layout), 32 floats per thread
    const float4* __restrict__ Cq = reinterpret_cast<const float4*>(g_c) + (size_t)g * 256;
    float4 c4[8];
    #pragma unroll
    for (int eq = 0; eq < 8; ++eq) c4[eq] = Cq[eq*32 + lane];

    float4 acc4[8];
    #pragma unroll
    for (int eq = 0; eq < 8; ++eq) acc4[eq] = make_float4(0.f, 0.f, 0.f, 0.f);

    const int* __restrict__ idxp = g_idx + (size_t)g * KMAX;
    const float SQRTD = 5.656854249492381f;   // sqrt(32)

    for (int k = wq; k < K; k += 4) {
        const int m = __ldg(idxp + k);
        const float4* __restrict__ Aq = reinterpret_cast<const float4*>(g_A) + (size_t)m * 256;
        const float gvv = __ldg(g_v + (size_t)m*DD + lane);

        float4 x[8];
        #pragma unroll
        for (int eq = 0; eq < 8; ++eq) x[eq] = Aq[eq*32 + lane];

        float rs0 = 0.f, rs1 = 0.f, rs2 = 0.f, rs3 = 0.f;
        #pragma unroll
        for (int eq = 0; eq < 8; ++eq) {
            x[eq].x += c4[eq].x; x[eq].y += c4[eq].y;
            x[eq].z += c4[eq].z; x[eq].w += c4[eq].w;
            rs0 += fabsf(x[eq].x); rs1 += fabsf(x[eq].y);
            rs2 += fabsf(x[eq].z); rs3 += fabsf(x[eq].w);
        }
        const float rs = (rs0 + rs1) + (rs2 + rs3);
        const float coef = gvv * __fdividef(SQRTD, rs + 3.2e-6f);  // + D*1e-7

        #pragma unroll
        for (int eq = 0; eq < 8; ++eq) {
            acc4[eq].x = fmaf(coef, x[eq].x, acc4[eq].x);
            acc4[eq].y = fmaf(coef, x[eq].y, acc4[eq].y);
            acc4[eq].z = fmaf(coef, x[eq].z, acc4[eq].z);
            acc4[eq].w = fmaf(coef, x[eq].w, acc4[eq].w);
        }
    }

    // one-time cross-lane reduction (component i corresponds to output e = i)
    float* accf = reinterpret_cast<float*>(acc4);
    #pragma unroll
    for (int i = 0; i < 32; ++i) {
        float v = accf[i];
        v += __shfl_xor_sync(0xFFFFFFFFu, v, 16);
        v += __shfl_xor_sync(0xFFFFFFFFu, v, 8);
        v += __shfl_xor_sync(0xFFFFFFFFu, v, 4);
        v += __shfl_xor_sync(0xFFFFFFFFu, v, 2);
        v += __shfl_xor_sync(0xFFFFFFFFu, v, 1);
        if (lane == 0) s_fin[w][i] = v;
    }
    __syncthreads();

    if (wq == 0) {
        const int b0 = pw * 4;
        const float tot = s_fin[b0][lane] + s_fin[b0+1][lane]
                        + s_fin[b0+2][lane] + s_fin[b0+3][lane];
        float o2 = b_s[lane];
        #pragma unroll
        for (int e = 0; e < DD; ++e) {
            const float te = __shfl_sync(0xFFFFFFFFu, tot, e);
            o2 = fmaf(te, W_s[e*DD + lane], o2);
        }
        out[(size_t)g*DD + lane] = o2;
    }
}

// Write trailing N scalar if the harness output includes the tuple's second element
__global__ void tail_kernel(float* __restrict__ out, int pos, float val)
{
    out[pos] = val;
}

// ---------------------------------------------------------------------------
extern "C" void kernel_launch(void* const* d_in, const int* in_sizes, int n_in,
                              void* d_out, int out_size)
{
    const float* feature = (const float*)d_in[0];
    const float* xyz     = (const float*)d_in[1];
    const float* W_r     = (const float*)d_in[2];
    const float* b_r     = (const float*)d_in[3];
    const float* W_v     = (const float*)d_in[4];
    const float* b_v     = (const float*)d_in[5];
    const float* W_s     = (const float*)d_in[6];
    const float* b_s     = (const float*)d_in[7];
    const int*   knnp    = (const int*)d_in[8];
    float* out = (float*)d_out;

    int* idx_out;
    cudaGetSymbolAddress((void**)&idx_out, g_idx);  // host-side address query (no alloc)

    knn_kernel<<<BN, 256>>>(xyz, knnp, idx_out);
    prep_kernel<<<dim3(BN/16, DD2/128), 256>>>(feature, xyz, W_r, b_r);
    v_kernel<<<(BN*DD + 255)/256, 256>>>(feature, xyz, W_v, b_v);
    main_kernel<<<BN/2, 256>>>(knnp, W_s, b_s, out);

    const int total = BN * DD;
    if (out_size > total) {
        tail_kernel<<<1, 1>>>(out, total, (float)NN);
    }
}

// round 4
// speedup vs baseline: 2.2836x; 1.3068x over previous
#include <cuda_runtime.h>
#include <cuda_fp16.h>
#include <math.h>

// Fixed problem shape (per reference setup_inputs)
#define BB   2
#define NN   2048
#define CC   32
#define CP3  35          // C + 3
#define DD   32
#define DD2  1024        // D*D
#define BN   (BB*NN)     // 4096
#define KMAX 64

// Scratch (allocation-free rule: __device__ globals)
// A (fp16) and c (fp32) stored in "quad" layout per point:
// flat index (e>>2)*128 + d*4 + (e&3) for weight[d][e]; a warp (lane=d) reads
// a whole row slice as one coalesced 8B/16B load per e-quad.
__device__ __align__(16) __half g_A[(size_t)BN * DD2];   // pre @ W_r1            (8 MB)
__device__ __align__(16) float  g_c[(size_t)BN * DD2];   // pre @ (W_r2-W_r1)+b_r (16 MB)
__device__ float g_v[BN * DD];            // relu(pre@W_v+b_v)
__device__ int   g_idx[BN * KMAX];        // flat neighbor indices (b*N+j)

// ---------------------------------------------------------------------------
// Kernel 1: exact KNN. One 11-bit-histogram pass + exact ranking of the
// boundary bucket (reproduces top_k smallest-index tie-break).
// one block per query point, 256 threads
// ---------------------------------------------------------------------------
__global__ void knn_kernel(const float* __restrict__ xyz,
                           const int* __restrict__ knnp,
                           int* __restrict__ idx_out)
{
    __shared__ unsigned s_u[NN];          // 8 KB: sortable keys
    __shared__ int      s_hist[2048];     // 8 KB: 11-bit histogram, reused as cand list
    __shared__ int      s_wsum[8];
    __shared__ int      s_bucket, s_less, s_cnt, s_c;

    const int g    = blockIdx.x;          // 0..BN-1
    const int base = (g / NN) * NN;       // batch base
    const int tid  = threadIdx.x;
    const int lane = tid & 31;
    const int w    = tid >> 5;
    const int K    = *knnp;

    const float xq = xyz[g*3+0], yq = xyz[g*3+1], zq = xyz[g*3+2];
    const float d2q = xq*xq + yq*yq + zq*zq;

    for (int i = tid; i < 2048; i += 256) s_hist[i] = 0;
    if (tid == 0) { s_cnt = 0; s_c = 0; }
    __syncthreads();

    // distances -> sortable uint keys + 11-bit histogram (warp-aggregated)
    for (int j = tid; j < NN; j += 256) {   // NN % 256 == 0: all lanes active
        const float x = xyz[(base+j)*3+0];
        const float y = xyz[(base+j)*3+1];
        const float z = xyz[(base+j)*3+2];
        const float d2j = x*x + y*y + z*z;
        const float dt  = x*xq + y*yq + z*zq;
        const float dist = (d2q + d2j) - 2.0f * dt;   // reference formula
        const unsigned bits = __float_as_uint(dist);
        const unsigned u = (bits & 0x80000000u) ? ~bits : (bits | 0x80000000u);
        s_u[j] = u;
        const unsigned bk = u >> 21;
        const unsigned mm = __match_any_sync(0xFFFFFFFFu, bk);
        if (lane == (__ffs(mm) - 1))
            atomicAdd(&s_hist[bk], __popc(mm));
    }
    __syncthreads();

    // find bucket containing rank K: thread t owns bins [8t, 8t+8)
    const int lo = tid * 8;
    int h[8]; int lsum = 0;
    #pragma unroll
    for (int i = 0; i < 8; ++i) { h[i] = s_hist[lo + i]; lsum += h[i]; }
    int incl = lsum;
    #pragma unroll
    for (int o = 1; o < 32; o <<= 1) {
        const int v = __shfl_up_sync(0xFFFFFFFFu, incl, o);
        if (lane >= o) incl += v;
    }
    if (lane == 31) s_wsum[w] = incl;
    __syncthreads();
    int woff = 0;
    #pragma unroll
    for (int i = 0; i < 8; ++i) if (i < w) woff += s_wsum[i];
    const int texcl = woff + incl - lsum;      // exclusive prefix for this thread's bins
    if (texcl < K && K <= woff + incl) {
        int cum = texcl;
        #pragma unroll
        for (int i = 0; i < 8; ++i) {
            if (cum + h[i] >= K) { s_bucket = lo + i; s_less = cum; break; }
            cum += h[i];
        }
    }
    __syncthreads();
    const unsigned B  = (unsigned)s_bucket;
    const int less    = s_less;
    const int rneed   = K - less;
    int* s_cand = s_hist;                     // histogram no longer needed

    // emit all strictly-smaller buckets (exactly `less` of them, order-free),
    // compact boundary bucket candidates
    for (int j = tid; j < NN; j += 256) {
        const unsigned u = s_u[j];
        const unsigned bk = u >> 21;
        if (bk < B) {
            const int p = atomicAdd(&s_cnt, 1);
            idx_out[(size_t)g*KMAX + p] = base + j;
        } else if (bk == B) {
            const int p = atomicAdd(&s_c, 1);
            s_cand[p] = j;
        }
    }
    __syncthreads();

    // exact rank (value, then index) within boundary bucket -> positions [less, K)
    const int c = s_c;
    for (int ci = tid; ci < c; ci += 256) {
        const int j = s_cand[ci];
        const unsigned u = s_u[j];
        int rank = 0;
        for (int i = 0; i < c; ++i) {
            const int ji = s_cand[i];
            const unsigned ui = s_u[ji];
            rank += (ui < u) || (ui == u && ji < j);
        }
        if (rank < rneed)
            idx_out[(size_t)g*KMAX + less + rank] = base + j;
    }
}

// ---------------------------------------------------------------------------
// Kernel 2: A = pre @ W_r1 (fp16) ; c = pre @ (W_r2 - W_r1) + b_r (fp32)
// quad layout; tile 32 points x 128 cols, 256 threads, 4pt x 4col per thread
// ---------------------------------------------------------------------------
#define PTS 32
__global__ void prep_kernel(const float* __restrict__ feature,
                            const float* __restrict__ xyz,
                            const float* __restrict__ W_r,
                            const float* __restrict__ b_r)
{
    __shared__ float s_pre[PTS][CP3 + 1];
    __shared__ float s_w1[CP3][128];
    __shared__ float s_wd[CP3][128];

    const int p0  = blockIdx.x * PTS;
    const int c0  = blockIdx.y * 128;
    const int tid = threadIdx.x;

    for (int t = tid; t < PTS * CP3; t += 256) {
        const int p = t / CP3, i = t % CP3;
        const int gg = p0 + p;
        s_pre[p][i] = (i < CC) ? feature[(size_t)gg*CC + i] : xyz[(size_t)gg*3 + (i - CC)];
    }
    for (int t = tid; t < CP3 * 128; t += 256) {
        const int i = t >> 7, cc = t & 127;
        const float w1 = W_r[(size_t)i*DD2 + c0 + cc];
        const float w2 = W_r[(size_t)(CP3 + i)*DD2 + c0 + cc];
        s_w1[i][cc] = w1;
        s_wd[i][cc] = w2 - w1;
    }
    __syncthreads();

    const int cq  = tid & 31;        // col group (4 cols)
    const int prg = tid >> 5;        // point group: points prg + pp*8
    const int cb  = cq * 4;

    float accA[4][4] = {};
    float accC[4][4] = {};

    for (int i = 0; i < CP3; ++i) {
        const float4 w1 = *reinterpret_cast<const float4*>(&s_w1[i][cb]);
        const float4 wd = *reinterpret_cast<const float4*>(&s_wd[i][cb]);
        #pragma unroll
        for (int pp = 0; pp < 4; ++pp) {
            const float pv = s_pre[prg + pp*8][i];   // warp-uniform -> broadcast
            accA[pp][0] = fmaf(pv, w1.x, accA[pp][0]);
            accA[pp][1] = fmaf(pv, w1.y, accA[pp][1]);
            accA[pp][2] = fmaf(pv, w1.z, accA[pp][2]);
            accA[pp][3] = fmaf(pv, w1.w, accA[pp][3]);
            accC[pp][0] = fmaf(pv, wd.x, accC[pp][0]);
            accC[pp][1] = fmaf(pv, wd.y, accC[pp][1]);
            accC[pp][2] = fmaf(pv, wd.z, accC[pp][2]);
            accC[pp][3] = fmaf(pv, wd.w, accC[pp][3]);
        }
    }

    // quad-layout destination: col = d*32 + e ; flat_q = (e>>2)*128 + d*4 + (e&3)
    const int col0  = c0 + cb;              // multiple of 4
    const int dRow  = col0 >> 5;
    const int eBase = col0 & 31;            // multiple of 4
    const int qoff  = (eBase >> 2) * 128 + dRow * 4;

    const float br0 = __ldg(b_r + col0 + 0), br1 = __ldg(b_r + col0 + 1);
    const float br2 = __ldg(b_r + col0 + 2), br3 = __ldg(b_r + col0 + 3);

    #pragma unroll
    for (int pp = 0; pp < 4; ++pp) {
        const int gg = p0 + prg + pp * 8;
        const size_t off = (size_t)gg * DD2 + qoff;
        // A in fp16 (two half2 stores, 8B total, 8B-aligned)
        *reinterpret_cast<__half2*>(&g_A[off])     = __floats2half2_rn(accA[pp][0], accA[pp][1]);
        *reinterpret_cast<__half2*>(&g_A[off + 2]) = __floats2half2_rn(accA[pp][2], accA[pp][3]);
        // c in fp32
        *reinterpret_cast<float4*>(&g_c[off]) =
            make_float4(accC[pp][0] + br0, accC[pp][1] + br1,
                        accC[pp][2] + br2, accC[pp][3] + br3);
    }
}

// ---------------------------------------------------------------------------
// Kernel 3: v = relu(pre @ W_v + b_v)
// ---------------------------------------------------------------------------
__global__ void v_kernel(const float* __restrict__ feature,
                         const float* __restrict__ xyz,
                         const float* __restrict__ W_v,
                         const float* __restrict__ b_v)
{
    const int t = blockIdx.x * 256 + threadIdx.x;
    if (t >= BN * DD) return;
    const int gg = t / DD, d = t % DD;
    float acc = b_v[d];
    #pragma unroll 8
    for (int i = 0; i < CC; ++i)
        acc = fmaf(feature[(size_t)gg*CC + i], W_v[i*DD + d], acc);
    #pragma unroll
    for (int i = 0; i < 3; ++i)
        acc = fmaf(xyz[(size_t)gg*3 + i], W_v[(CC + i)*DD + d], acc);
    g_v[t] = fmaxf(acc, 0.0f);
}

// ---------------------------------------------------------------------------
// Kernel 4: main aggregation, direct-LDG fp16 quad layout.
// 256 threads = 8 warps = 2 points (4 warps/point). lane = d (weight row).
// Per k: 8 coalesced LDG.64 (fp16) of the A-row slice, row abs-sum in
// registers, accumulate in registers. No smem staging, no per-k sync.
// ---------------------------------------------------------------------------
__global__ void __launch_bounds__(256)
main_kernel(const int* __restrict__ knnp,
            const float* __restrict__ W_s,
            const float* __restrict__ b_s,
            float* __restrict__ out)
{
    __shared__ float s_fin[8][DD];

    const int tid  = threadIdx.x;
    const int lane = tid & 31;
    const int w    = tid >> 5;
    const int pw   = w >> 2;             // point within block (0/1)
    const int wq   = w & 3;              // warp within point
    const int g    = blockIdx.x * 2 + pw;
    const int K    = *knnp;

    // c for this point (fp32 quad layout), 32 floats per thread
    const float4* __restrict__ Cq = reinterpret_cast<const float4*>(g_c) + (size_t)g * 256;
    float4 c4[8];
    #pragma unroll
    for (int eq = 0; eq < 8; ++eq) c4[eq] = Cq[eq*32 + lane];

    float4 acc4[8];
    #pragma unroll
    for (int eq = 0; eq < 8; ++eq) acc4[eq] = make_float4(0.f, 0.f, 0.f, 0.f);

    const int* __restrict__ idxp = g_idx + (size_t)g * KMAX;
    const float SQRTD = 5.656854249492381f;   // sqrt(32)

    for (int k = wq; k < K; k += 4) {
        const int m = __ldg(idxp + k);
        const uint2* __restrict__ Aq =
            reinterpret_cast<const uint2*>(g_A + (size_t)m * DD2);
        const float gvv = __ldg(g_v + (size_t)m*DD + lane);

        uint2 r[8];
        #pragma unroll
        for (int eq = 0; eq < 8; ++eq) r[eq] = Aq[eq*32 + lane];

        float4 x[8];
        float rs0 = 0.f, rs1 = 0.f, rs2 = 0.f, rs3 = 0.f;
        #pragma unroll
        for (int eq = 0; eq < 8; ++eq) {
            const __half2 h0 = *reinterpret_cast<const __half2*>(&r[eq].x);
            const __half2 h1 = *reinterpret_cast<const __half2*>(&r[eq].y);
            const float2 f0 = __half22float2(h0);
            const float2 f1 = __half22float2(h1);
            x[eq].x = f0.x + c4[eq].x; x[eq].y = f0.y + c4[eq].y;
            x[eq].z = f1.x + c4[eq].z; x[eq].w = f1.y + c4[eq].w;
            rs0 += fabsf(x[eq].x); rs1 += fabsf(x[eq].y);
            rs2 += fabsf(x[eq].z); rs3 += fabsf(x[eq].w);
        }
        const float rs = (rs0 + rs1) + (rs2 + rs3);
        const float coef = gvv * __fdividef(SQRTD, rs + 3.2e-6f);  // + D*1e-7

        #pragma unroll
        for (int eq = 0; eq < 8; ++eq) {
            acc4[eq].x = fmaf(coef, x[eq].x, acc4[eq].x);
            acc4[eq].y = fmaf(coef, x[eq].y, acc4[eq].y);
            acc4[eq].z = fmaf(coef, x[eq].z, acc4[eq].z);
            acc4[eq].w = fmaf(coef, x[eq].w, acc4[eq].w);
        }
    }

    // one-time cross-lane reduction (component i corresponds to output e = i)
    float* accf = reinterpret_cast<float*>(acc4);
    #pragma unroll
    for (int i = 0; i < 32; ++i) {
        float v = accf[i];
        v += __shfl_xor_sync(0xFFFFFFFFu, v, 16);
        v += __shfl_xor_sync(0xFFFFFFFFu, v, 8);
        v += __shfl_xor_sync(0xFFFFFFFFu, v, 4);
        v += __shfl_xor_sync(0xFFFFFFFFu, v, 2);
        v += __shfl_xor_sync(0xFFFFFFFFu, v, 1);
        if (lane == 0) s_fin[w][i] = v;
    }
    __syncthreads();

    if (wq == 0) {
        const int b0 = pw * 4;
        const float tot = s_fin[b0][lane] + s_fin[b0+1][lane]
                        + s_fin[b0+2][lane] + s_fin[b0+3][lane];
        float o2 = b_s[lane];
        #pragma unroll
        for (int e = 0; e < DD; ++e) {
            const float te = __shfl_sync(0xFFFFFFFFu, tot, e);
            o2 = fmaf(te, W_s[e*DD + lane], o2);
        }
        out[(size_t)g*DD + lane] = o2;
    }
}

// Write trailing N scalar if the harness output includes the tuple's second element
__global__ void tail_kernel(float* __restrict__ out, int pos, float val)
{
    out[pos] = val;
}

// ---------------------------------------------------------------------------
extern "C" void kernel_launch(void* const* d_in, const int* in_sizes, int n_in,
                              void* d_out, int out_size)
{
    const float* feature = (const float*)d_in[0];
    const float* xyz     = (const float*)d_in[1];
    const float* W_r     = (const float*)d_in[2];
    const float* b_r     = (const float*)d_in[3];
    const float* W_v     = (const float*)d_in[4];
    const float* b_v     = (const float*)d_in[5];
    const float* W_s     = (const float*)d_in[6];
    const float* b_s     = (const float*)d_in[7];
    const int*   knnp    = (const int*)d_in[8];
    float* out = (float*)d_out;

    int* idx_out;
    cudaGetSymbolAddress((void**)&idx_out, g_idx);  // host-side address query (no alloc)

    knn_kernel<<<BN, 256>>>(xyz, knnp, idx_out);
    prep_kernel<<<dim3(BN/PTS, DD2/128), 256>>>(feature, xyz, W_r, b_r);
    v_kernel<<<(BN*DD + 255)/256, 256>>>(feature, xyz, W_v, b_v);
    main_kernel<<<BN/2, 256>>>(knnp, W_s, b_s, out);

    const int total = BN * DD;
    if (out_size > total) {
        tail_kernel<<<1, 1>>>(out, total, (float)NN);
    }
}

// round 5
// speedup vs baseline: 2.3700x; 1.0378x over previous
#include <cuda_runtime.h>
#include <cuda_fp16.h>
#include <math.h>

// Fixed problem shape (per reference setup_inputs)
#define BB   2
#define NN   2048
#define CC   32
#define CP3  35          // C + 3
#define DD   32
#define DD2  1024        // D*D
#define BN   (BB*NN)     // 4096
#define KMAX 64

// Scratch (allocation-free rule: __device__ globals)
// A and c (both fp16) in "quad" layout per point:
// flat index (e>>2)*128 + d*4 + (e&3) for weight[d][e]; a warp (lane=d) reads
// a whole row slice as coalesced 8B loads per e-quad.
__device__ __align__(16) __half g_A[(size_t)BN * DD2];   // pre @ W_r1            (8 MB)
__device__ __align__(16) __half g_c[(size_t)BN * DD2];   // pre @ (W_r2-W_r1)+b_r (8 MB)
__device__ float g_v[BN * DD];            // relu(pre@W_v+b_v)
__device__ int   g_idx[BN * KMAX];        // flat neighbor indices (b*N+j)

// ---------------------------------------------------------------------------
// Kernel 1: exact KNN. One 11-bit-histogram pass + exact ranking of the
// boundary bucket (reproduces top_k smallest-index tie-break).
// one block per query point, 256 threads
// ---------------------------------------------------------------------------
__global__ void knn_kernel(const float* __restrict__ xyz,
                           const int* __restrict__ knnp,
                           int* __restrict__ idx_out)
{
    __shared__ unsigned s_u[NN];          // 8 KB: sortable keys
    __shared__ int      s_hist[2048];     // 8 KB: 11-bit histogram, reused as cand list
    __shared__ int      s_wsum[8];
    __shared__ int      s_bucket, s_less, s_cnt, s_c;

    const int g    = blockIdx.x;          // 0..BN-1
    const int base = (g / NN) * NN;       // batch base
    const int tid  = threadIdx.x;
    const int lane = tid & 31;
    const int w    = tid >> 5;
    const int K    = *knnp;

    const float xq = xyz[g*3+0], yq = xyz[g*3+1], zq = xyz[g*3+2];
    const float d2q = xq*xq + yq*yq + zq*zq;

    for (int i = tid; i < 2048; i += 256) s_hist[i] = 0;
    if (tid == 0) { s_cnt = 0; s_c = 0; }
    __syncthreads();

    // distances -> sortable uint keys + 11-bit histogram (warp-aggregated)
    for (int j = tid; j < NN; j += 256) {   // NN % 256 == 0: all lanes active
        const float x = xyz[(base+j)*3+0];
        const float y = xyz[(base+j)*3+1];
        const float z = xyz[(base+j)*3+2];
        const float d2j = x*x + y*y + z*z;
        const float dt  = x*xq + y*yq + z*zq;
        const float dist = (d2q + d2j) - 2.0f * dt;   // reference formula
        const unsigned bits = __float_as_uint(dist);
        const unsigned u = (bits & 0x80000000u) ? ~bits : (bits | 0x80000000u);
        s_u[j] = u;
        const unsigned bk = u >> 21;
        const unsigned mm = __match_any_sync(0xFFFFFFFFu, bk);
        if (lane == (__ffs(mm) - 1))
            atomicAdd(&s_hist[bk], __popc(mm));
    }
    __syncthreads();

    // find bucket containing rank K: thread t owns bins [8t, 8t+8)
    const int lo = tid * 8;
    int h[8]; int lsum = 0;
    #pragma unroll
    for (int i = 0; i < 8; ++i) { h[i] = s_hist[lo + i]; lsum += h[i]; }
    int incl = lsum;
    #pragma unroll
    for (int o = 1; o < 32; o <<= 1) {
        const int v = __shfl_up_sync(0xFFFFFFFFu, incl, o);
        if (lane >= o) incl += v;
    }
    if (lane == 31) s_wsum[w] = incl;
    __syncthreads();
    int woff = 0;
    #pragma unroll
    for (int i = 0; i < 8; ++i) if (i < w) woff += s_wsum[i];
    const int texcl = woff + incl - lsum;      // exclusive prefix for this thread's bins
    if (texcl < K && K <= woff + incl) {
        int cum = texcl;
        #pragma unroll
        for (int i = 0; i < 8; ++i) {
            if (cum + h[i] >= K) { s_bucket = lo + i; s_less = cum; break; }
            cum += h[i];
        }
    }
    __syncthreads();
    const unsigned B  = (unsigned)s_bucket;
    const int less    = s_less;
    const int rneed   = K - less;
    int* s_cand = s_hist;                     // histogram no longer needed

    // emit all strictly-smaller buckets (exactly `less` of them, order-free),
    // compact boundary bucket candidates
    for (int j = tid; j < NN; j += 256) {
        const unsigned u = s_u[j];
        const unsigned bk = u >> 21;
        if (bk < B) {
            const int p = atomicAdd(&s_cnt, 1);
            idx_out[(size_t)g*KMAX + p] = base + j;
        } else if (bk == B) {
            const int p = atomicAdd(&s_c, 1);
            s_cand[p] = j;
        }
    }
    __syncthreads();

    // exact rank (value, then index) within boundary bucket -> positions [less, K)
    const int c = s_c;
    for (int ci = tid; ci < c; ci += 256) {
        const int j = s_cand[ci];
        const unsigned u = s_u[j];
        int rank = 0;
        for (int i = 0; i < c; ++i) {
            const int ji = s_cand[i];
            const unsigned ui = s_u[ji];
            rank += (ui < u) || (ui == u && ji < j);
        }
        if (rank < rneed)
            idx_out[(size_t)g*KMAX + less + rank] = base + j;
    }
}

// ---------------------------------------------------------------------------
// Kernel 2: A = pre @ W_r1 ; c = pre @ (W_r2 - W_r1) + b_r   (both fp16, quad)
// tile 32 points x 128 cols, 256 threads, 4pt x 4col per thread
// ---------------------------------------------------------------------------
#define PTS 32
__global__ void prep_kernel(const float* __restrict__ feature,
                            const float* __restrict__ xyz,
                            const float* __restrict__ W_r,
                            const float* __restrict__ b_r)
{
    __shared__ float s_pre[PTS][CP3 + 1];
    __shared__ float s_w1[CP3][128];
    __shared__ float s_wd[CP3][128];

    const int p0  = blockIdx.x * PTS;
    const int c0  = blockIdx.y * 128;
    const int tid = threadIdx.x;

    for (int t = tid; t < PTS * CP3; t += 256) {
        const int p = t / CP3, i = t % CP3;
        const int gg = p0 + p;
        s_pre[p][i] = (i < CC) ? feature[(size_t)gg*CC + i] : xyz[(size_t)gg*3 + (i - CC)];
    }
    for (int t = tid; t < CP3 * 128; t += 256) {
        const int i = t >> 7, cc = t & 127;
        const float w1 = W_r[(size_t)i*DD2 + c0 + cc];
        const float w2 = W_r[(size_t)(CP3 + i)*DD2 + c0 + cc];
        s_w1[i][cc] = w1;
        s_wd[i][cc] = w2 - w1;
    }
    __syncthreads();

    const int cq  = tid & 31;        // col group (4 cols)
    const int prg = tid >> 5;        // point group: points prg + pp*8
    const int cb  = cq * 4;

    float accA[4][4] = {};
    float accC[4][4] = {};

    for (int i = 0; i < CP3; ++i) {
        const float4 w1 = *reinterpret_cast<const float4*>(&s_w1[i][cb]);
        const float4 wd = *reinterpret_cast<const float4*>(&s_wd[i][cb]);
        #pragma unroll
        for (int pp = 0; pp < 4; ++pp) {
            const float pv = s_pre[prg + pp*8][i];   // warp-uniform -> broadcast
            accA[pp][0] = fmaf(pv, w1.x, accA[pp][0]);
            accA[pp][1] = fmaf(pv, w1.y, accA[pp][1]);
            accA[pp][2] = fmaf(pv, w1.z, accA[pp][2]);
            accA[pp][3] = fmaf(pv, w1.w, accA[pp][3]);
            accC[pp][0] = fmaf(pv, wd.x, accC[pp][0]);
            accC[pp][1] = fmaf(pv, wd.y, accC[pp][1]);
            accC[pp][2] = fmaf(pv, wd.z, accC[pp][2]);
            accC[pp][3] = fmaf(pv, wd.w, accC[pp][3]);
        }
    }

    // quad-layout destination: col = d*32 + e ; flat_q = (e>>2)*128 + d*4 + (e&3)
    const int col0  = c0 + cb;              // multiple of 4
    const int dRow  = col0 >> 5;
    const int eBase = col0 & 31;            // multiple of 4
    const int qoff  = (eBase >> 2) * 128 + dRow * 4;

    const float br0 = __ldg(b_r + col0 + 0), br1 = __ldg(b_r + col0 + 1);
    const float br2 = __ldg(b_r + col0 + 2), br3 = __ldg(b_r + col0 + 3);

    #pragma unroll
    for (int pp = 0; pp < 4; ++pp) {
        const int gg = p0 + prg + pp * 8;
        const size_t off = (size_t)gg * DD2 + qoff;
        *reinterpret_cast<__half2*>(&g_A[off])     = __floats2half2_rn(accA[pp][0], accA[pp][1]);
        *reinterpret_cast<__half2*>(&g_A[off + 2]) = __floats2half2_rn(accA[pp][2], accA[pp][3]);
        *reinterpret_cast<__half2*>(&g_c[off])     = __floats2half2_rn(accC[pp][0] + br0, accC[pp][1] + br1);
        *reinterpret_cast<__half2*>(&g_c[off + 2]) = __floats2half2_rn(accC[pp][2] + br2, accC[pp][3] + br3);
    }
}

// ---------------------------------------------------------------------------
// Kernel 3: v = relu(pre @ W_v + b_v)
// ---------------------------------------------------------------------------
__global__ void v_kernel(const float* __restrict__ feature,
                         const float* __restrict__ xyz,
                         const float* __restrict__ W_v,
                         const float* __restrict__ b_v)
{
    const int t = blockIdx.x * 256 + threadIdx.x;
    if (t >= BN * DD) return;
    const int gg = t / DD, d = t % DD;
    float acc = b_v[d];
    #pragma unroll 8
    for (int i = 0; i < CC; ++i)
        acc = fmaf(feature[(size_t)gg*CC + i], W_v[i*DD + d], acc);
    #pragma unroll
    for (int i = 0; i < 3; ++i)
        acc = fmaf(xyz[(size_t)gg*3 + i], W_v[(CC + i)*DD + d], acc);
    g_v[t] = fmaxf(acc, 0.0f);
}

// ---------------------------------------------------------------------------
// Kernel 4: main aggregation, half2 SIMD pipeline.
// 256 threads = 8 warps = 2 points (4 warps/point). lane = d (weight row).
// x = HADD2(A, c); row abs-sum via HADD2 |mod| chains; HFMA2 into half2
// partials, flushed to fp32 every 3 k. Epilogue: smem transpose reduce.
// ---------------------------------------------------------------------------
#define EPI_PITCH 36
__global__ void __launch_bounds__(256)
main_kernel(const int* __restrict__ knnp,
            const float* __restrict__ W_s,
            const float* __restrict__ b_s,
            float* __restrict__ out)
{
    __shared__ float s_acc[8][32][EPI_PITCH];   // 36 KB
    __shared__ float s_p[8][DD];

    const int tid  = threadIdx.x;
    const int lane = tid & 31;
    const int w    = tid >> 5;
    const int pw   = w >> 2;             // point within block (0/1)
    const int wq   = w & 3;              // warp within point
    const int g    = blockIdx.x * 2 + pw;
    const int K    = *knnp;

    // c for this point (fp16 quad layout): 16 half2 per thread
    const uint2* __restrict__ Cq =
        reinterpret_cast<const uint2*>(g_c + (size_t)g * DD2) + lane;
    __half2 ch[16];
    #pragma unroll
    for (int eq = 0; eq < 8; ++eq) {
        const uint2 cr = Cq[eq*32];
        ch[2*eq]   = *reinterpret_cast<const __half2*>(&cr.x);
        ch[2*eq+1] = *reinterpret_cast<const __half2*>(&cr.y);
    }

    float accf[DD];
    #pragma unroll
    for (int e = 0; e < DD; ++e) accf[e] = 0.0f;

    const int* __restrict__ idxp = g_idx + (size_t)g * KMAX;
    const float SQRTD = 5.656854249492381f;   // sqrt(32)
    const __half2 HZERO = __float2half2_rn(0.0f);

    int k = wq;
    #pragma unroll 1
    while (k < K) {
        __half2 hacc[16];
        #pragma unroll
        for (int i = 0; i < 16; ++i) hacc[i] = HZERO;

        #pragma unroll 1
        for (int t = 0; t < 3 && k < K; ++t, k += 4) {
            const int m = __ldg(idxp + k);
            const uint2* __restrict__ Aq =
                reinterpret_cast<const uint2*>(g_A + (size_t)m * DD2) + lane;
            const float gvv = __ldg(g_v + (size_t)m*DD + lane);

            uint2 r[8];
            #pragma unroll
            for (int eq = 0; eq < 8; ++eq) r[eq] = Aq[eq*32];

            __half2 xh[16];
            __half2 rs0 = HZERO, rs1 = HZERO;
            #pragma unroll
            for (int eq = 0; eq < 8; ++eq) {
                const __half2 a0 = *reinterpret_cast<const __half2*>(&r[eq].x);
                const __half2 a1 = *reinterpret_cast<const __half2*>(&r[eq].y);
                xh[2*eq]   = __hadd2(a0, ch[2*eq]);
                xh[2*eq+1] = __hadd2(a1, ch[2*eq+1]);
                rs0 = __hadd2(rs0, __habs2(xh[2*eq]));
                rs1 = __hadd2(rs1, __habs2(xh[2*eq+1]));
            }
            const float2 f0 = __half22float2(rs0);
            const float2 f1 = __half22float2(rs1);
            const float rs = (f0.x + f0.y) + (f1.x + f1.y);
            const float coef = gvv * __fdividef(SQRTD, rs + 3.2e-6f);  // + D*1e-7
            const __half2 c2 = __float2half2_rn(coef);

            #pragma unroll
            for (int i = 0; i < 16; ++i)
                hacc[i] = __hfma2(c2, xh[i], hacc[i]);
        }

        // flush half partials to fp32
        #pragma unroll
        for (int i = 0; i < 16; ++i) {
            const float2 f = __half22float2(hacc[i]);
            accf[2*i]   += f.x;
            accf[2*i+1] += f.y;
        }
    }

    // epilogue: smem transpose reduce (pitch 36 -> conflict-free both ways)
    #pragma unroll
    for (int q = 0; q < 8; ++q)
        *reinterpret_cast<float4*>(&s_acc[w][lane][q*4]) =
            make_float4(accf[4*q], accf[4*q+1], accf[4*q+2], accf[4*q+3]);
    __syncthreads();

    // each warp reduces its own 32 d-rows: lane e sums column e
    {
        float s = 0.0f;
        #pragma unroll
        for (int d = 0; d < 32; ++d) s += s_acc[w][d][lane];
        s_p[w][lane] = s;
    }
    __syncthreads();

    if (wq == 0) {
        const int b0 = pw * 4;
        const float tot = s_p[b0][lane] + s_p[b0+1][lane]
                        + s_p[b0+2][lane] + s_p[b0+3][lane];
        float o2 = b_s[lane];
        #pragma unroll
        for (int e = 0; e < DD; ++e) {
            const float te = __shfl_sync(0xFFFFFFFFu, tot, e);
            o2 = fmaf(te, W_s[e*DD + lane], o2);
        }
        out[(size_t)g*DD + lane] = o2;
    }
}

// Write trailing N scalar if the harness output includes the tuple's second element
__global__ void tail_kernel(float* __restrict__ out, int pos, float val)
{
    out[pos] = val;
}

// ---------------------------------------------------------------------------
extern "C" void kernel_launch(void* const* d_in, const int* in_sizes, int n_in,
                              void* d_out, int out_size)
{
    const float* feature = (const float*)d_in[0];
    const float* xyz     = (const float*)d_in[1];
    const float* W_r     = (const float*)d_in[2];
    const float* b_r     = (const float*)d_in[3];
    const float* W_v     = (const float*)d_in[4];
    const float* b_v     = (const float*)d_in[5];
    const float* W_s     = (const float*)d_in[6];
    const float* b_s     = (const float*)d_in[7];
    const int*   knnp    = (const int*)d_in[8];
    float* out = (float*)d_out;

    int* idx_out;
    cudaGetSymbolAddress((void**)&idx_out, g_idx);  // host-side address query (no alloc)

    knn_kernel<<<BN, 256>>>(xyz, knnp, idx_out);
    prep_kernel<<<dim3(BN/PTS, DD2/128), 256>>>(feature, xyz, W_r, b_r);
    v_kernel<<<(BN*DD + 255)/256, 256>>>(feature, xyz, W_v, b_v);
    main_kernel<<<BN/2, 256>>>(knnp, W_s, b_s, out);

    const int total = BN * DD;
    if (out_size > total) {
        tail_kernel<<<1, 1>>>(out, total, (float)NN);
    }
}

// round 6
// speedup vs baseline: 2.5933x; 1.0942x over previous
#include <cuda_runtime.h>
#include <cuda_fp16.h>
#include <math.h>

// Fixed problem shape (per reference setup_inputs)
#define BB   2
#define NN   2048
#define CC   32
#define CP3  35          // C + 3
#define DD   32
#define DD2  1024        // D*D
#define BN   (BB*NN)     // 4096
#define KMAX 64

// Scratch (allocation-free rule: __device__ globals)
// A and c (both fp16) in "quad" layout per point:
// flat index (e>>2)*128 + d*4 + (e&3) for weight[d][e].
__device__ __align__(16) __half g_A[(size_t)BN * DD2];   // pre @ W_r1            (8 MB)
__device__ __align__(16) __half g_c[(size_t)BN * DD2];   // pre @ (W_r2-W_r1)+b_r (8 MB)
__device__ float g_v[BN * DD];            // relu(pre@W_v+b_v)
__device__ int   g_idx[BN * KMAX];        // flat neighbor indices (b*N+j)

// ---------------------------------------------------------------------------
// Kernel 1: exact KNN. One 11-bit-histogram pass + exact ranking of the
// boundary bucket (reproduces top_k smallest-index tie-break).
// one block per query point, 256 threads
// ---------------------------------------------------------------------------
__global__ void knn_kernel(const float* __restrict__ xyz,
                           const int* __restrict__ knnp,
                           int* __restrict__ idx_out)
{
    __shared__ unsigned s_u[NN];          // 8 KB: sortable keys
    __shared__ int      s_hist[2048];     // 8 KB: 11-bit histogram, reused as cand list
    __shared__ int      s_wsum[8];
    __shared__ int      s_bucket, s_less, s_cnt, s_c;

    const int g    = blockIdx.x;          // 0..BN-1
    const int base = (g / NN) * NN;       // batch base
    const int tid  = threadIdx.x;
    const int lane = tid & 31;
    const int w    = tid >> 5;
    const int K    = *knnp;

    const float xq = xyz[g*3+0], yq = xyz[g*3+1], zq = xyz[g*3+2];
    const float d2q = xq*xq + yq*yq + zq*zq;

    for (int i = tid; i < 2048; i += 256) s_hist[i] = 0;
    if (tid == 0) { s_cnt = 0; s_c = 0; }
    __syncthreads();

    // distances -> sortable uint keys + 11-bit histogram (warp-aggregated)
    for (int j = tid; j < NN; j += 256) {   // NN % 256 == 0: all lanes active
        const float x = xyz[(base+j)*3+0];
        const float y = xyz[(base+j)*3+1];
        const float z = xyz[(base+j)*3+2];
        const float d2j = x*x + y*y + z*z;
        const float dt  = x*xq + y*yq + z*zq;
        const float dist = (d2q + d2j) - 2.0f * dt;   // reference formula
        const unsigned bits = __float_as_uint(dist);
        const unsigned u = (bits & 0x80000000u) ? ~bits : (bits | 0x80000000u);
        s_u[j] = u;
        const unsigned bk = u >> 21;
        const unsigned mm = __match_any_sync(0xFFFFFFFFu, bk);
        if (lane == (__ffs(mm) - 1))
            atomicAdd(&s_hist[bk], __popc(mm));
    }
    __syncthreads();

    // find bucket containing rank K: thread t owns bins [8t, 8t+8)
    const int lo = tid * 8;
    int h[8]; int lsum = 0;
    #pragma unroll
    for (int i = 0; i < 8; ++i) { h[i] = s_hist[lo + i]; lsum += h[i]; }
    int incl = lsum;
    #pragma unroll
    for (int o = 1; o < 32; o <<= 1) {
        const int v = __shfl_up_sync(0xFFFFFFFFu, incl, o);
        if (lane >= o) incl += v;
    }
    if (lane == 31) s_wsum[w] = incl;
    __syncthreads();
    int woff = 0;
    #pragma unroll
    for (int i = 0; i < 8; ++i) if (i < w) woff += s_wsum[i];
    const int texcl = woff + incl - lsum;      // exclusive prefix for this thread's bins
    if (texcl < K && K <= woff + incl) {
        int cum = texcl;
        #pragma unroll
        for (int i = 0; i < 8; ++i) {
            if (cum + h[i] >= K) { s_bucket = lo + i; s_less = cum; break; }
            cum += h[i];
        }
    }
    __syncthreads();
    const unsigned B  = (unsigned)s_bucket;
    const int less    = s_less;
    const int rneed   = K - less;
    int* s_cand = s_hist;                     // histogram no longer needed

    // emit all strictly-smaller buckets (exactly `less` of them, order-free),
    // compact boundary bucket candidates
    for (int j = tid; j < NN; j += 256) {
        const unsigned u = s_u[j];
        const unsigned bk = u >> 21;
        if (bk < B) {
            const int p = atomicAdd(&s_cnt, 1);
            idx_out[(size_t)g*KMAX + p] = base + j;
        } else if (bk == B) {
            const int p = atomicAdd(&s_c, 1);
            s_cand[p] = j;
        }
    }
    __syncthreads();

    // exact rank (value, then index) within boundary bucket -> positions [less, K)
    const int c = s_c;
    for (int ci = tid; ci < c; ci += 256) {
        const int j = s_cand[ci];
        const unsigned u = s_u[j];
        int rank = 0;
        for (int i = 0; i < c; ++i) {
            const int ji = s_cand[i];
            const unsigned ui = s_u[ji];
            rank += (ui < u) || (ui == u && ji < j);
        }
        if (rank < rneed)
            idx_out[(size_t)g*KMAX + less + rank] = base + j;
    }
}

// ---------------------------------------------------------------------------
// Kernel 2: A = pre @ W_r1 ; c = pre @ (W_r2 - W_r1) + b_r  (both fp16, quad)
// + fused v = relu(pre @ W_v + b_v) on blockIdx.y == 0 blocks.
// tile 32 points x 128 cols, 256 threads, 4pt x 4col per thread
// ---------------------------------------------------------------------------
#define PTS 32
__global__ void prep_kernel(const float* __restrict__ feature,
                            const float* __restrict__ xyz,
                            const float* __restrict__ W_r,
                            const float* __restrict__ b_r,
                            const float* __restrict__ W_v,
                            const float* __restrict__ b_v)
{
    __shared__ float s_pre[PTS][CP3 + 1];
    __shared__ float s_w1[CP3][128];
    __shared__ float s_wd[CP3][128];

    const int p0  = blockIdx.x * PTS;
    const int c0  = blockIdx.y * 128;
    const int tid = threadIdx.x;

    for (int t = tid; t < PTS * CP3; t += 256) {
        const int p = t / CP3, i = t % CP3;
        const int gg = p0 + p;
        s_pre[p][i] = (i < CC) ? feature[(size_t)gg*CC + i] : xyz[(size_t)gg*3 + (i - CC)];
    }
    for (int t = tid; t < CP3 * 128; t += 256) {
        const int i = t >> 7, cc = t & 127;
        const float w1 = W_r[(size_t)i*DD2 + c0 + cc];
        const float w2 = W_r[(size_t)(CP3 + i)*DD2 + c0 + cc];
        s_w1[i][cc] = w1;
        s_wd[i][cc] = w2 - w1;
    }
    __syncthreads();

    const int cq  = tid & 31;        // col group (4 cols)
    const int prg = tid >> 5;        // point group: points prg + pp*8
    const int cb  = cq * 4;

    float accA[4][4] = {};
    float accC[4][4] = {};

    for (int i = 0; i < CP3; ++i) {
        const float4 w1 = *reinterpret_cast<const float4*>(&s_w1[i][cb]);
        const float4 wd = *reinterpret_cast<const float4*>(&s_wd[i][cb]);
        #pragma unroll
        for (int pp = 0; pp < 4; ++pp) {
            const float pv = s_pre[prg + pp*8][i];   // warp-uniform -> broadcast
            accA[pp][0] = fmaf(pv, w1.x, accA[pp][0]);
            accA[pp][1] = fmaf(pv, w1.y, accA[pp][1]);
            accA[pp][2] = fmaf(pv, w1.z, accA[pp][2]);
            accA[pp][3] = fmaf(pv, w1.w, accA[pp][3]);
            accC[pp][0] = fmaf(pv, wd.x, accC[pp][0]);
            accC[pp][1] = fmaf(pv, wd.y, accC[pp][1]);
            accC[pp][2] = fmaf(pv, wd.z, accC[pp][2]);
            accC[pp][3] = fmaf(pv, wd.w, accC[pp][3]);
        }
    }

    // quad-layout destination: col = d*32 + e ; flat_q = (e>>2)*128 + d*4 + (e&3)
    const int col0  = c0 + cb;              // multiple of 4
    const int dRow  = col0 >> 5;
    const int eBase = col0 & 31;            // multiple of 4
    const int qoff  = (eBase >> 2) * 128 + dRow * 4;

    const float br0 = __ldg(b_r + col0 + 0), br1 = __ldg(b_r + col0 + 1);
    const float br2 = __ldg(b_r + col0 + 2), br3 = __ldg(b_r + col0 + 3);

    #pragma unroll
    for (int pp = 0; pp < 4; ++pp) {
        const int gg = p0 + prg + pp * 8;
        const size_t off = (size_t)gg * DD2 + qoff;
        *reinterpret_cast<__half2*>(&g_A[off])     = __floats2half2_rn(accA[pp][0], accA[pp][1]);
        *reinterpret_cast<__half2*>(&g_A[off + 2]) = __floats2half2_rn(accA[pp][2], accA[pp][3]);
        *reinterpret_cast<__half2*>(&g_c[off])     = __floats2half2_rn(accC[pp][0] + br0, accC[pp][1] + br1);
        *reinterpret_cast<__half2*>(&g_c[off + 2]) = __floats2half2_rn(accC[pp][2] + br2, accC[pp][3] + br3);
    }

    // fused v = relu(pre @ W_v + b_v) using the staged s_pre
    if (blockIdx.y == 0) {
        for (int t = tid; t < PTS * DD; t += 256) {
            const int p = t >> 5, d = t & 31;
            float acc = __ldg(b_v + d);
            #pragma unroll 7
            for (int i = 0; i < CP3; ++i)
                acc = fmaf(s_pre[p][i], __ldg(W_v + i*DD + d), acc);
            g_v[(size_t)(p0 + p)*DD + d] = fmaxf(acc, 0.0f);
        }
    }
}

// ---------------------------------------------------------------------------
// Kernel 4: main aggregation, split-row half2 pipeline.
// 256 threads = 8 warps = 2 points. Per point: 2 k-units x 2 d-half warps.
// lane = eh*16 + d': thread owns rows d = dhalf*16+d', e in [eh*16, eh*16+16).
// Row abs-sum completed by shfl_xor(16). HFMA2 partials flushed to a
// per-warp smem region (pitch 33, conflict-free) every 3 k.
// ---------------------------------------------------------------------------
#define EPI_PITCH 33
__global__ void __launch_bounds__(256)
main_kernel(const int* __restrict__ knnp,
            const float* __restrict__ W_s,
            const float* __restrict__ b_s,
            float* __restrict__ out)
{
    __shared__ float s_acc[8][16][EPI_PITCH];   // 16.5 KB, per-warp regions

    const int tid   = threadIdx.x;
    const int lane  = tid & 31;
    const int w     = tid >> 5;
    const int pw    = w >> 2;             // point within block (0/1)
    const int wq    = w & 3;              // warp within point
    const int unit  = wq >> 1;            // k-parity unit (0/1)
    const int dhalf = wq & 1;             // which 16 rows
    const int dp    = lane & 15;
    const int eh    = lane >> 4;          // which 16 cols
    const int d     = dhalf * 16 + dp;
    const int g     = blockIdx.x * 2 + pw;
    const int K     = *knnp;

    // zero own region
    for (int i = lane; i < 16 * EPI_PITCH; i += 32)
        (&s_acc[w][0][0])[i] = 0.0f;
    __syncwarp();

    // c half-row: quads eq = eh*4 + q, uint2 index = eq*32 + d
    const uint2* __restrict__ Cq = reinterpret_cast<const uint2*>(g_c + (size_t)g * DD2);
    __half2 ch[8];
    #pragma unroll
    for (int q = 0; q < 4; ++q) {
        const uint2 cr = Cq[(eh*4 + q)*32 + d];
        ch[2*q]   = *reinterpret_cast<const __half2*>(&cr.x);
        ch[2*q+1] = *reinterpret_cast<const __half2*>(&cr.y);
    }

    const int* __restrict__ idxp = g_idx + (size_t)g * KMAX;
    const float SQRTD = 5.656854249492381f;   // sqrt(32)
    const __half2 HZ = __float2half2_rn(0.0f);

    int k = unit;
    #pragma unroll 1
    while (k < K) {
        __half2 hacc[8];
        #pragma unroll
        for (int i = 0; i < 8; ++i) hacc[i] = HZ;

        #pragma unroll 1
        for (int t = 0; t < 3 && k < K; ++t, k += 2) {
            const int m = __ldg(idxp + k);
            const uint2* __restrict__ Aq =
                reinterpret_cast<const uint2*>(g_A + (size_t)m * DD2);
            const float gvv = __ldg(g_v + (size_t)m*DD + d);

            uint2 r[4];
            #pragma unroll
            for (int q = 0; q < 4; ++q) r[q] = Aq[(eh*4 + q)*32 + d];

            __half2 xh[8];
            __half2 rsh = HZ;
            #pragma unroll
            for (int q = 0; q < 4; ++q) {
                const __half2 a0 = *reinterpret_cast<const __half2*>(&r[q].x);
                const __half2 a1 = *reinterpret_cast<const __half2*>(&r[q].y);
                xh[2*q]   = __hadd2(a0, ch[2*q]);
                xh[2*q+1] = __hadd2(a1, ch[2*q+1]);
                rsh = __hadd2(rsh, __habs2(xh[2*q]));
                rsh = __hadd2(rsh, __habs2(xh[2*q+1]));
            }
            const float2 fr = __half22float2(rsh);
            float rs = fr.x + fr.y;
            rs += __shfl_xor_sync(0xFFFFFFFFu, rs, 16);     // full row sum
            const float coef = gvv * __fdividef(SQRTD, rs + 3.2e-6f);  // + D*1e-7
            const __half2 c2 = __float2half2_rn(coef);

            #pragma unroll
            for (int i = 0; i < 8; ++i)
                hacc[i] = __hfma2(c2, xh[i], hacc[i]);
        }

        // flush half partials into per-warp smem region (conflict-free)
        #pragma unroll
        for (int i = 0; i < 8; ++i) {
            const float2 f = __half22float2(hacc[i]);
            const int e0 = eh*16 + (i >> 1)*4 + (i & 1)*2;
            s_acc[w][dp][e0]     += f.x;
            s_acc[w][dp][e0 + 1] += f.y;
        }
    }
    __syncthreads();

    // epilogue: sum the point's 4 warp regions over all 16 d' rows, then W_s
    if (wq == 0) {
        const int b0 = pw * 4;
        float tot = 0.0f;
        #pragma unroll
        for (int dd = 0; dd < 16; ++dd)
            tot += (s_acc[b0][dd][lane]   + s_acc[b0+1][dd][lane])
                 + (s_acc[b0+2][dd][lane] + s_acc[b0+3][dd][lane]);
        float o2 = b_s[lane];
        #pragma unroll
        for (int e = 0; e < DD; ++e) {
            const float te = __shfl_sync(0xFFFFFFFFu, tot, e);
            o2 = fmaf(te, W_s[e*DD + lane], o2);
        }
        out[(size_t)g*DD + lane] = o2;
    }
}

// Write trailing N scalar if the harness output includes the tuple's second element
__global__ void tail_kernel(float* __restrict__ out, int pos, float val)
{
    out[pos] = val;
}

// ---------------------------------------------------------------------------
extern "C" void kernel_launch(void* const* d_in, const int* in_sizes, int n_in,
                              void* d_out, int out_size)
{
    const float* feature = (const float*)d_in[0];
    const float* xyz     = (const float*)d_in[1];
    const float* W_r     = (const float*)d_in[2];
    const float* b_r     = (const float*)d_in[3];
    const float* W_v     = (const float*)d_in[4];
    const float* b_v     = (const float*)d_in[5];
    const float* W_s     = (const float*)d_in[6];
    const float* b_s     = (const float*)d_in[7];
    const int*   knnp    = (const int*)d_in[8];
    float* out = (float*)d_out;

    int* idx_out;
    cudaGetSymbolAddress((void**)&idx_out, g_idx);  // host-side address query (no alloc)

    knn_kernel<<<BN, 256>>>(xyz, knnp, idx_out);
    prep_kernel<<<dim3(BN/PTS, DD2/128), 256>>>(feature, xyz, W_r, b_r, W_v, b_v);
    main_kernel<<<BN/2, 256>>>(knnp, W_s, b_s, out);

    const int total = BN * DD;
    if (out_size > total) {
        tail_kernel<<<1, 1>>>(out, total, (float)NN);
    }
}